// round 7
// baseline (speedup 1.0000x reference)
#include <cuda_runtime.h>
#include <cuda_fp16.h>

// GCN_56882546868697 — R7: bucketed CSR (no hist_r / no offsets — binning with
// zero-initialized cursors produces both the neighbor lists AND the in-degrees),
// fork/join dual-stream, shfl-distributed coalesced index batches in agg.

#define NN 100000
#define NE 1600000
#define DF 64
#define LT 64
#define NC 16
#define NEG 0.01f
#define CAP 128           // bucket capacity (P(deg>=128) < 1e-60 for Poisson(16))

// ---- static scratch ----
__device__ __align__(16) __half g_h[NN * LT];   // layer-1 pre-agg, fp16
__device__ __align__(16) __half g_z[NN * NC];   // layer-2 sigmoid acts, fp16
__device__ int g_degs[NN];                      // sender out-degree
__device__ int g_cur[NN];                       // bucket cursor == in-degree after bin
__device__ int g_buck[(size_t)NN * CAP];        // neighbor lists (senders), bucketed

// ---------------------------------------------------------------- zero cursors (branch A)
__global__ void k_zero_cur(int nn) {
    const int stride = gridDim.x * blockDim.x;
    for (int i = blockIdx.x * blockDim.x + threadIdx.x; i < nn; i += stride)
        g_cur[i] = 0;
}
// ---------------------------------------------------------------- zero sender degrees (branch B)
__global__ void k_init_s(int nn) {
    const int stride = gridDim.x * blockDim.x;
    for (int i = blockIdx.x * blockDim.x + threadIdx.x; i < nn; i += stride)
        g_degs[i] = 0;
}

// ---------------------------------------------------------------- sender-degree histogram
__global__ void k_hist_s(const int* __restrict__ senders, int ne) {
    int t = blockIdx.x * blockDim.x + threadIdx.x;
    int e0 = t * 4;
    if (e0 + 3 < ne) {
        int4 s = *reinterpret_cast<const int4*>(&senders[e0]);
        atomicAdd(&g_degs[s.x], 1); atomicAdd(&g_degs[s.y], 1);
        atomicAdd(&g_degs[s.z], 1); atomicAdd(&g_degs[s.w], 1);
    } else {
        for (int e = e0; e < ne; ++e) atomicAdd(&g_degs[__ldg(&senders[e])], 1);
    }
}

// ---------------------------------------------------------------- bucket binning
// cursor alloc + store; g_cur ends as the true in-degree (stores clamped to CAP)
__global__ void k_bin(const int* __restrict__ senders,
                      const int* __restrict__ receivers, int ne) {
    int t = blockIdx.x * blockDim.x + threadIdx.x;
    int e0 = t * 4;
    if (e0 + 3 < ne) {
        int4 s = *reinterpret_cast<const int4*>(&senders[e0]);
        int4 r = *reinterpret_cast<const int4*>(&receivers[e0]);
        int p0 = atomicAdd(&g_cur[r.x], 1);
        int p1 = atomicAdd(&g_cur[r.y], 1);
        int p2 = atomicAdd(&g_cur[r.z], 1);
        int p3 = atomicAdd(&g_cur[r.w], 1);
        if (p0 < CAP) g_buck[((size_t)r.x << 7) + p0] = s.x;
        if (p1 < CAP) g_buck[((size_t)r.y << 7) + p1] = s.y;
        if (p2 < CAP) g_buck[((size_t)r.z << 7) + p2] = s.z;
        if (p3 < CAP) g_buck[((size_t)r.w << 7) + p3] = s.w;
    } else {
        for (int e = e0; e < ne; ++e) {
            int r = __ldg(&receivers[e]);
            int p = atomicAdd(&g_cur[r], 1);
            if (p < CAP) g_buck[((size_t)r << 7) + p] = __ldg(&senders[e]);
        }
    }
}

// ---------------------------------------------------------------- GEMM1 + sender norm -> fp16
__global__ void k_gemm1(const float* __restrict__ nodes,
                        const float* __restrict__ W0,
                        const float* __restrict__ b0, int nn) {
    __shared__ __align__(16) float sW[DF * LT];
    __shared__ float sx[64][DF + 1];
    const int tid = threadIdx.x;
    const int row0 = blockIdx.x * 64;

    for (int i = tid; i < DF * LT; i += 256) sW[i] = W0[i];
    for (int idx = tid; idx < 64 * 16; idx += 256) {
        int r = idx >> 4, k0 = (idx & 15) * 4;
        int grow = row0 + r;
        float4 v = (grow < nn)
            ? *reinterpret_cast<const float4*>(&nodes[grow * DF + k0])
            : make_float4(0.f, 0.f, 0.f, 0.f);
        sx[r][k0] = v.x; sx[r][k0 + 1] = v.y; sx[r][k0 + 2] = v.z; sx[r][k0 + 3] = v.w;
    }
    __syncthreads();

    const int ty = tid >> 4, tx = tid & 15;
    const int r0 = ty * 4, c0 = tx * 4;

    unsigned long long acc[4][2];
#pragma unroll
    for (int i = 0; i < 4; ++i) { acc[i][0] = 0ull; acc[i][1] = 0ull; }

#pragma unroll
    for (int k = 0; k < DF; ++k) {
        ulonglong2 b2 = *reinterpret_cast<const ulonglong2*>(&sW[k * LT + c0]);
#pragma unroll
        for (int i = 0; i < 4; ++i) {
            float a = sx[r0 + i][k];
            unsigned long long ap;
            asm("mov.b64 %0, {%1, %1};" : "=l"(ap) : "r"(__float_as_uint(a)));
            asm("fma.rn.f32x2 %0, %1, %2, %0;" : "+l"(acc[i][0]) : "l"(ap), "l"(b2.x));
            asm("fma.rn.f32x2 %0, %1, %2, %0;" : "+l"(acc[i][1]) : "l"(ap), "l"(b2.y));
        }
    }

    const float4 bias = *reinterpret_cast<const float4*>(&b0[c0]);
#pragma unroll
    for (int i = 0; i < 4; ++i) {
        int grow = row0 + r0 + i;
        if (grow < nn) {
            unsigned lo0, hi0, lo1, hi1;
            asm("mov.b64 {%0, %1}, %2;" : "=r"(lo0), "=r"(hi0) : "l"(acc[i][0]));
            asm("mov.b64 {%0, %1}, %2;" : "=r"(lo1), "=r"(hi1) : "l"(acc[i][1]));
            float s = rsqrtf(fmaxf((float)g_degs[grow], 1.0f));
            float ox = (__uint_as_float(lo0) + bias.x) * s;
            float oy = (__uint_as_float(hi0) + bias.y) * s;
            float oz = (__uint_as_float(lo1) + bias.z) * s;
            float ow = (__uint_as_float(hi1) + bias.w) * s;
            __half2 h0 = __floats2half2_rn(ox, oy);
            __half2 h1 = __floats2half2_rn(oz, ow);
            uint2 st;
            st.x = *reinterpret_cast<unsigned*>(&h0);
            st.y = *reinterpret_cast<unsigned*>(&h1);
            *reinterpret_cast<uint2*>(&g_h[grow * LT + c0]) = st;
        }
    }
}

// ---------------------------------------------------------------- agg1 + norm + leaky + GEMM2 + sigmoid
// 256 thr = 16 nodes x 16 lanes. Indices loaded coalesced (16/lane-batch),
// distributed via width-16 segmented shfl; each lane gathers 8B of the row.
__global__ void k_agg1l2(const float* __restrict__ W1,
                         const float* __restrict__ b1, int nn) {
    __shared__ float sW1[LT * NC];         // [k][c]
    __shared__ float sact[16][LT + 1];
    const int tid = threadIdx.x;
    for (int i = tid; i < LT * NC; i += 256) sW1[i] = W1[i];

    const int ln  = tid >> 4;       // node slot 0..15
    const int l16 = tid & 15;       // lane within node group
    const int node = blockIdx.x * 16 + ln;
    const unsigned hmask = 0xFFFFu << ((tid & 31) & 16);  // my half-warp's mask

    if (node < nn) {
        int deg = g_cur[node];
        int cnt = min(deg, CAP);
        const int* bk = &g_buck[(size_t)node << 7];
        float ax = 0.f, ay = 0.f, az = 0.f, aw = 0.f;
        for (int b0 = 0; b0 < cnt; b0 += 16) {
            int t = b0 + l16;
            int idxr = (t < cnt) ? bk[t] : 0;   // coalesced 64B index batch
            int m = min(16, cnt - b0);
            for (int j = 0; j < m; ++j) {
                int s = __shfl_sync(hmask, idxr, j, 16);
                uint2 u = *reinterpret_cast<const uint2*>(&g_h[s * LT + l16 * 4]);
                float2 f0 = __half22float2(*reinterpret_cast<__half2*>(&u.x));
                float2 f1 = __half22float2(*reinterpret_cast<__half2*>(&u.y));
                ax += f0.x; ay += f0.y; az += f1.x; aw += f1.y;
            }
        }
        float dr = rsqrtf(fmaxf((float)deg, 1.0f));
        ax *= dr; ay *= dr; az *= dr; aw *= dr;
        ax = (ax >= 0.f) ? ax : NEG * ax;
        ay = (ay >= 0.f) ? ay : NEG * ay;
        az = (az >= 0.f) ? az : NEG * az;
        aw = (aw >= 0.f) ? aw : NEG * aw;
        sact[ln][l16 * 4 + 0] = ax;
        sact[ln][l16 * 4 + 1] = ay;
        sact[ln][l16 * 4 + 2] = az;
        sact[ln][l16 * 4 + 3] = aw;
    }
    __syncthreads();

    if (node >= nn) return;          // (ln, l16) reused as (row, out-col)
    float acc = __ldg(&b1[l16]);
#pragma unroll
    for (int k = 0; k < LT; ++k) acc += sact[ln][k] * sW1[k * NC + l16];
    float zz = 1.0f / (1.0f + __expf(-acc));
    g_z[node * NC + l16] = __float2half_rn(zz);
}

// ---------------------------------------------------------------- agg2: warp per node
// 32-index coalesced batches; 4 edges processed concurrently (4 slots x 8 cols);
// shfl-xor reduce over slots; lanes<8 write the 64B fp32 row.
__global__ void k_agg2(float* __restrict__ out, int nn) {
    const int tid = threadIdx.x;
    const int wid = tid >> 5;
    const int lane = tid & 31;
    const int node = blockIdx.x * 8 + wid;
    if (node >= nn) return;
    const int slot = lane >> 3;     // 0..3
    const int col  = lane & 7;      // 0..7
    int cnt = min(g_cur[node], CAP);
    const int* bk = &g_buck[(size_t)node << 7];
    float ax = 0.f, ay = 0.f;
    for (int b0 = 0; b0 < cnt; b0 += 32) {
        int t = b0 + lane;
        int idxr = (t < cnt) ? bk[t] : 0;   // coalesced 128B index batch
        int m = min(32, cnt - b0);
        for (int e = 0; e < m; e += 4) {
            int j = e + slot;
            int s = __shfl_sync(0xffffffffu, idxr, j & 31, 32);
            if (j < m) {
                unsigned u = *reinterpret_cast<const unsigned*>(&g_z[s * NC + col * 2]);
                float2 f = __half22float2(*reinterpret_cast<__half2*>(&u));
                ax += f.x; ay += f.y;
            }
        }
    }
    ax += __shfl_xor_sync(0xffffffffu, ax, 8);
    ay += __shfl_xor_sync(0xffffffffu, ay, 8);
    ax += __shfl_xor_sync(0xffffffffu, ax, 16);
    ay += __shfl_xor_sync(0xffffffffu, ay, 16);
    if (lane < 8) {
        float2 o; o.x = ax; o.y = ay;
        *reinterpret_cast<float2*>(&out[node * NC + col * 2]) = o;
    }
}

// ---------------------------------------------------------------- launch (fork/join)
extern "C" void kernel_launch(void* const* d_in, const int* in_sizes, int n_in,
                              void* d_out, int out_size) {
    const float* nodes     = (const float*)d_in[0];
    const int*   senders   = (const int*)  d_in[1];
    const int*   receivers = (const int*)  d_in[2];
    const float* W0        = (const float*)d_in[3];
    const float* b0        = (const float*)d_in[4];
    const float* W1        = (const float*)d_in[5];
    const float* b1        = (const float*)d_in[6];
    float*       out       = (float*)d_out;

    const int nn = in_sizes[0] / DF;       // 100000
    const int ne = in_sizes[1];            // 1600000
    const int eg = ((ne + 3) / 4 + 255) / 256;

    static cudaStream_t s2 = 0;
    static cudaEvent_t evFork = 0, evJoin = 0;
    if (!s2) {
        cudaStreamCreateWithFlags(&s2, cudaStreamNonBlocking);
        cudaEventCreateWithFlags(&evFork, cudaEventDisableTiming);
        cudaEventCreateWithFlags(&evJoin, cudaEventDisableTiming);
    }

    // fork at t=0
    cudaEventRecord(evFork, 0);
    cudaStreamWaitEvent(s2, evFork, 0);

    // branch B (s2): zero degs -> hist_s -> GEMM1
    k_init_s<<<256, 256, 0, s2>>>(nn);
    k_hist_s<<<eg, 256, 0, s2>>>(senders, ne);
    k_gemm1<<<(nn + 63) / 64, 256, 0, s2>>>(nodes, W0, b0, nn);
    cudaEventRecord(evJoin, s2);

    // branch A (s0): zero cursors -> bucket bin (no hist_r, no offsets!)
    k_zero_cur<<<256, 256>>>(nn);
    k_bin<<<eg, 256>>>(senders, receivers, ne);

    // join: agg needs buckets (A) + g_h (B)
    cudaStreamWaitEvent(0, evJoin, 0);
    k_agg1l2<<<(nn + 15) / 16, 256>>>(W1, b1, nn);
    k_agg2<<<(nn + 7) / 8, 256>>>(out, nn);
}

// round 8
// speedup vs baseline: 1.1141x; 1.1141x over previous
#include <cuda_runtime.h>
#include <cuda_fp16.h>

// GCN_56882546868697 — R8 = R5 (best: 129.1us) + bucketed CSR (deletes
// hist_r + offsets kernels) + memset-based init. Aggregation kernels are
// byte-identical to R5 except bucket addressing (base = node*128, deg = g_cur).

#define NN 100000
#define NE 1600000
#define DF 64
#define LT 64
#define NC 16
#define NEG 0.01f
#define CAP 128    // bucket capacity; P(Poisson(16) >= 128) < 1e-60 per node

// ---- static scratch ----
__device__ __align__(16) __half g_h[NN * LT];   // layer-1 pre-agg, fp16
__device__ __align__(16) __half g_z[NN * NC];   // layer-2 sigmoid acts, fp16
__device__ int g_degs[NN];                      // sender out-degree
__device__ int g_cur[NN];                       // bucket cursor == in-degree after bin
__device__ int g_buck[(size_t)NN * CAP];        // bucketed neighbor (sender) lists

// ---------------------------------------------------------------- sender-degree histogram
__global__ void k_hist_s(const int* __restrict__ senders, int ne) {
    int t = blockIdx.x * blockDim.x + threadIdx.x;
    int e0 = t * 4;
    if (e0 + 3 < ne) {
        int4 s = *reinterpret_cast<const int4*>(&senders[e0]);
        atomicAdd(&g_degs[s.x], 1); atomicAdd(&g_degs[s.y], 1);
        atomicAdd(&g_degs[s.z], 1); atomicAdd(&g_degs[s.w], 1);
    } else {
        for (int e = e0; e < ne; ++e) atomicAdd(&g_degs[__ldg(&senders[e])], 1);
    }
}

// ---------------------------------------------------------------- bucket binning
// cursor alloc + store; g_cur ends as the TRUE in-degree (stores clamped to CAP)
__global__ void k_bin(const int* __restrict__ senders,
                      const int* __restrict__ receivers, int ne) {
    int t = blockIdx.x * blockDim.x + threadIdx.x;
    int e0 = t * 4;
    if (e0 + 3 < ne) {
        int4 s = *reinterpret_cast<const int4*>(&senders[e0]);
        int4 r = *reinterpret_cast<const int4*>(&receivers[e0]);
        int p0 = atomicAdd(&g_cur[r.x], 1);
        int p1 = atomicAdd(&g_cur[r.y], 1);
        int p2 = atomicAdd(&g_cur[r.z], 1);
        int p3 = atomicAdd(&g_cur[r.w], 1);
        if (p0 < CAP) g_buck[((size_t)r.x << 7) + p0] = s.x;
        if (p1 < CAP) g_buck[((size_t)r.y << 7) + p1] = s.y;
        if (p2 < CAP) g_buck[((size_t)r.z << 7) + p2] = s.z;
        if (p3 < CAP) g_buck[((size_t)r.w << 7) + p3] = s.w;
    } else {
        for (int e = e0; e < ne; ++e) {
            int r = __ldg(&receivers[e]);
            int p = atomicAdd(&g_cur[r], 1);
            if (p < CAP) g_buck[((size_t)r << 7) + p] = __ldg(&senders[e]);
        }
    }
}

// ---------------------------------------------------------------- GEMM1 + sender norm -> fp16
__global__ void k_gemm1(const float* __restrict__ nodes,
                        const float* __restrict__ W0,
                        const float* __restrict__ b0, int nn) {
    __shared__ __align__(16) float sW[DF * LT];
    __shared__ float sx[64][DF + 1];
    const int tid = threadIdx.x;
    const int row0 = blockIdx.x * 64;

    for (int i = tid; i < DF * LT; i += 256) sW[i] = W0[i];
    for (int idx = tid; idx < 64 * 16; idx += 256) {
        int r = idx >> 4, k0 = (idx & 15) * 4;
        int grow = row0 + r;
        float4 v = (grow < nn)
            ? *reinterpret_cast<const float4*>(&nodes[grow * DF + k0])
            : make_float4(0.f, 0.f, 0.f, 0.f);
        sx[r][k0] = v.x; sx[r][k0 + 1] = v.y; sx[r][k0 + 2] = v.z; sx[r][k0 + 3] = v.w;
    }
    __syncthreads();

    const int ty = tid >> 4, tx = tid & 15;
    const int r0 = ty * 4, c0 = tx * 4;

    unsigned long long acc[4][2];
#pragma unroll
    for (int i = 0; i < 4; ++i) { acc[i][0] = 0ull; acc[i][1] = 0ull; }

#pragma unroll
    for (int k = 0; k < DF; ++k) {
        ulonglong2 b2 = *reinterpret_cast<const ulonglong2*>(&sW[k * LT + c0]);
#pragma unroll
        for (int i = 0; i < 4; ++i) {
            float a = sx[r0 + i][k];
            unsigned long long ap;
            asm("mov.b64 %0, {%1, %1};" : "=l"(ap) : "r"(__float_as_uint(a)));
            asm("fma.rn.f32x2 %0, %1, %2, %0;" : "+l"(acc[i][0]) : "l"(ap), "l"(b2.x));
            asm("fma.rn.f32x2 %0, %1, %2, %0;" : "+l"(acc[i][1]) : "l"(ap), "l"(b2.y));
        }
    }

    const float4 bias = *reinterpret_cast<const float4*>(&b0[c0]);
#pragma unroll
    for (int i = 0; i < 4; ++i) {
        int grow = row0 + r0 + i;
        if (grow < nn) {
            unsigned lo0, hi0, lo1, hi1;
            asm("mov.b64 {%0, %1}, %2;" : "=r"(lo0), "=r"(hi0) : "l"(acc[i][0]));
            asm("mov.b64 {%0, %1}, %2;" : "=r"(lo1), "=r"(hi1) : "l"(acc[i][1]));
            float s = rsqrtf(fmaxf((float)g_degs[grow], 1.0f));
            float ox = (__uint_as_float(lo0) + bias.x) * s;
            float oy = (__uint_as_float(hi0) + bias.y) * s;
            float oz = (__uint_as_float(lo1) + bias.z) * s;
            float ow = (__uint_as_float(hi1) + bias.w) * s;
            __half2 h0 = __floats2half2_rn(ox, oy);
            __half2 h1 = __floats2half2_rn(oz, ow);
            uint2 st;
            st.x = *reinterpret_cast<unsigned*>(&h0);
            st.y = *reinterpret_cast<unsigned*>(&h1);
            *reinterpret_cast<uint2*>(&g_h[grow * LT + c0]) = st;
        }
    }
}

// ---------------------------------------------------------------- agg1 + norm + leaky + GEMM2 + sigmoid
// (R5 layout: 256 thr = 16 nodes x 16 lanes, 4x-unrolled broadcast-index loads)
__global__ void k_agg1l2(const float* __restrict__ W1,
                         const float* __restrict__ b1, int nn) {
    __shared__ float sW1[LT * NC];          // [k][c]
    __shared__ float sact[16][LT + 1];
    const int tid = threadIdx.x;
    for (int i = tid; i < LT * NC; i += 256) sW1[i] = W1[i];

    const int ln = tid >> 4;
    const int c  = tid & 15;
    const int node = blockIdx.x * 16 + ln;

    if (node < nn) {
        int deg = g_cur[node];
        int cnt = min(deg, CAP);
        const int* bk = &g_buck[(size_t)node << 7];
        float ax = 0.f, ay = 0.f, az = 0.f, aw = 0.f;
        int i = 0;
        for (; i + 4 <= cnt; i += 4) {
            int s0 = __ldg(&bk[i]);
            int s1 = __ldg(&bk[i + 1]);
            int s2 = __ldg(&bk[i + 2]);
            int s3 = __ldg(&bk[i + 3]);
            uint2 u0 = *reinterpret_cast<const uint2*>(&g_h[s0 * LT + c * 4]);
            uint2 u1 = *reinterpret_cast<const uint2*>(&g_h[s1 * LT + c * 4]);
            uint2 u2 = *reinterpret_cast<const uint2*>(&g_h[s2 * LT + c * 4]);
            uint2 u3 = *reinterpret_cast<const uint2*>(&g_h[s3 * LT + c * 4]);
            float2 a0 = __half22float2(*reinterpret_cast<__half2*>(&u0.x));
            float2 b0_ = __half22float2(*reinterpret_cast<__half2*>(&u0.y));
            float2 a1 = __half22float2(*reinterpret_cast<__half2*>(&u1.x));
            float2 b1_ = __half22float2(*reinterpret_cast<__half2*>(&u1.y));
            float2 a2 = __half22float2(*reinterpret_cast<__half2*>(&u2.x));
            float2 b2_ = __half22float2(*reinterpret_cast<__half2*>(&u2.y));
            float2 a3 = __half22float2(*reinterpret_cast<__half2*>(&u3.x));
            float2 b3_ = __half22float2(*reinterpret_cast<__half2*>(&u3.y));
            ax += a0.x + a1.x + a2.x + a3.x;
            ay += a0.y + a1.y + a2.y + a3.y;
            az += b0_.x + b1_.x + b2_.x + b3_.x;
            aw += b0_.y + b1_.y + b2_.y + b3_.y;
        }
        for (; i < cnt; ++i) {
            int s = __ldg(&bk[i]);
            uint2 u = *reinterpret_cast<const uint2*>(&g_h[s * LT + c * 4]);
            float2 f0 = __half22float2(*reinterpret_cast<__half2*>(&u.x));
            float2 f1 = __half22float2(*reinterpret_cast<__half2*>(&u.y));
            ax += f0.x; ay += f0.y; az += f1.x; aw += f1.y;
        }
        float dr = rsqrtf(fmaxf((float)deg, 1.0f));
        ax *= dr; ay *= dr; az *= dr; aw *= dr;
        ax = (ax >= 0.f) ? ax : NEG * ax;
        ay = (ay >= 0.f) ? ay : NEG * ay;
        az = (az >= 0.f) ? az : NEG * az;
        aw = (aw >= 0.f) ? aw : NEG * aw;
        sact[ln][c * 4 + 0] = ax;
        sact[ln][c * 4 + 1] = ay;
        sact[ln][c * 4 + 2] = az;
        sact[ln][c * 4 + 3] = aw;
    }
    __syncthreads();

    if (node >= nn) return;
    float acc = __ldg(&b1[c]);
#pragma unroll
    for (int k = 0; k < LT; ++k) acc += sact[ln][k] * sW1[k * NC + c];
    float zz = 1.0f / (1.0f + __expf(-acc));
    g_z[node * NC + c] = __float2half_rn(zz);
}

// ---------------------------------------------------------------- agg2 (R5 layout: 2 thr/node)
__global__ void k_agg2(float* __restrict__ out, int nn) {
    const int t = blockIdx.x * blockDim.x + threadIdx.x;
    const int node = t >> 1;
    const int c = t & 1;
    if (node >= nn) return;
    int cnt = min(g_cur[node], CAP);
    const int* bk = &g_buck[(size_t)node << 7];
    float a[8] = {};
    int i = 0;
    for (; i + 2 <= cnt; i += 2) {
        int s0 = __ldg(&bk[i]);
        int s1 = __ldg(&bk[i + 1]);
        uint4 u0 = *reinterpret_cast<const uint4*>(&g_z[s0 * NC + c * 8]);
        uint4 u1 = *reinterpret_cast<const uint4*>(&g_z[s1 * NC + c * 8]);
        float2 f;
        f = __half22float2(*reinterpret_cast<__half2*>(&u0.x)); a[0] += f.x; a[1] += f.y;
        f = __half22float2(*reinterpret_cast<__half2*>(&u0.y)); a[2] += f.x; a[3] += f.y;
        f = __half22float2(*reinterpret_cast<__half2*>(&u0.z)); a[4] += f.x; a[5] += f.y;
        f = __half22float2(*reinterpret_cast<__half2*>(&u0.w)); a[6] += f.x; a[7] += f.y;
        f = __half22float2(*reinterpret_cast<__half2*>(&u1.x)); a[0] += f.x; a[1] += f.y;
        f = __half22float2(*reinterpret_cast<__half2*>(&u1.y)); a[2] += f.x; a[3] += f.y;
        f = __half22float2(*reinterpret_cast<__half2*>(&u1.z)); a[4] += f.x; a[5] += f.y;
        f = __half22float2(*reinterpret_cast<__half2*>(&u1.w)); a[6] += f.x; a[7] += f.y;
    }
    for (; i < cnt; ++i) {
        int s = __ldg(&bk[i]);
        uint4 u = *reinterpret_cast<const uint4*>(&g_z[s * NC + c * 8]);
        float2 f;
        f = __half22float2(*reinterpret_cast<__half2*>(&u.x)); a[0] += f.x; a[1] += f.y;
        f = __half22float2(*reinterpret_cast<__half2*>(&u.y)); a[2] += f.x; a[3] += f.y;
        f = __half22float2(*reinterpret_cast<__half2*>(&u.z)); a[4] += f.x; a[5] += f.y;
        f = __half22float2(*reinterpret_cast<__half2*>(&u.w)); a[6] += f.x; a[7] += f.y;
    }
    float4 o0 = make_float4(a[0], a[1], a[2], a[3]);
    float4 o1 = make_float4(a[4], a[5], a[6], a[7]);
    *reinterpret_cast<float4*>(&out[node * NC + c * 8])     = o0;
    *reinterpret_cast<float4*>(&out[node * NC + c * 8 + 4]) = o1;
}

// ---------------------------------------------------------------- launch (fork/join)
extern "C" void kernel_launch(void* const* d_in, const int* in_sizes, int n_in,
                              void* d_out, int out_size) {
    const float* nodes     = (const float*)d_in[0];
    const int*   senders   = (const int*)  d_in[1];
    const int*   receivers = (const int*)  d_in[2];
    const float* W0        = (const float*)d_in[3];
    const float* b0        = (const float*)d_in[4];
    const float* W1        = (const float*)d_in[5];
    const float* b1        = (const float*)d_in[6];
    float*       out       = (float*)d_out;

    const int nn = in_sizes[0] / DF;       // 100000
    const int ne = in_sizes[1];            // 1600000
    const int eg = ((ne + 3) / 4 + 255) / 256;

    static cudaStream_t s2 = 0;
    static cudaEvent_t evFork = 0, evJoin = 0;
    static void *p_cur = 0, *p_degs = 0;
    if (!s2) {
        cudaStreamCreateWithFlags(&s2, cudaStreamNonBlocking);
        cudaEventCreateWithFlags(&evFork, cudaEventDisableTiming);
        cudaEventCreateWithFlags(&evJoin, cudaEventDisableTiming);
        cudaGetSymbolAddress(&p_cur, g_cur);
        cudaGetSymbolAddress(&p_degs, g_degs);
    }

    // fork at t=0
    cudaEventRecord(evFork, 0);
    cudaStreamWaitEvent(s2, evFork, 0);

    // branch B (s2): zero degs -> hist_s -> GEMM1
    cudaMemsetAsync(p_degs, 0, (size_t)nn * sizeof(int), s2);
    k_hist_s<<<eg, 256, 0, s2>>>(senders, ne);
    k_gemm1<<<(nn + 63) / 64, 256, 0, s2>>>(nodes, W0, b0, nn);
    cudaEventRecord(evJoin, s2);

    // branch A (s0): zero cursors -> bucket bin (no hist_r, no offsets)
    cudaMemsetAsync(p_cur, 0, (size_t)nn * sizeof(int), 0);
    k_bin<<<eg, 256>>>(senders, receivers, ne);

    // join: agg needs buckets (A) + g_h (B)
    cudaStreamWaitEvent(0, evJoin, 0);
    k_agg1l2<<<(nn + 15) / 16, 256>>>(W1, b1, nn);
    k_agg2<<<(nn * 2 + 255) / 256, 256>>>(out, nn);
}